// round 2
// baseline (speedup 1.0000x reference)
#include <cuda_runtime.h>
#include <cuda_bf16.h>

// EdgeNetwork: out = tanh(relu(cat(h[dst], h[src], dR) @ W1 + b1) @ W2 + b2)
// E=640000, F=128, K1=257, MID=192, OUT=128. All fp32.
//
// Round-0 baseline: fp32 SIMT tiled GEMM, 64 edges per block, 256 threads,
// packed fma.rn.f32x2 accumulators (sm_103a FFMA2, PTX-only pattern).

#define E_TOTAL 640000
#define FDIM    128
#define K1      257
#define MID     192
#define OUTD    128
#define TILE_E  64
#define LDI     260   // padded pitch of input tile (257 -> 260, 16B aligned rows)
#define LDH     196   // padded pitch of hidden tile
#define NTHREADS 256

// smem float offsets
#define S_INP   0                    // [64][260] = 16640
#define S_W     16640                // staging: max(16*192, 16*128) = 3072
#define S_HID   19712                // [64][196] = 12544
#define SMEM_FLOATS 32256            // = 129024 bytes

// ---- packed f32x2 helpers ----
__device__ __forceinline__ unsigned long long pk2(float lo, float hi) {
    unsigned long long r;
    asm("mov.b64 %0, {%1, %2};" : "=l"(r) : "f"(lo), "f"(hi));
    return r;
}
__device__ __forceinline__ void upk2(unsigned long long v, float& lo, float& hi) {
    asm("mov.b64 {%0, %1}, %2;" : "=f"(lo), "=f"(hi) : "l"(v));
}
__device__ __forceinline__ void fma2(unsigned long long& d,
                                     unsigned long long a,
                                     unsigned long long b) {
    asm("fma.rn.f32x2 %0, %1, %2, %0;" : "+l"(d) : "l"(a), "l"(b));
}

__global__ void __launch_bounds__(NTHREADS, 1)
edge_mlp_kernel(const float* __restrict__ h,
                const float* __restrict__ dR,
                const int*   __restrict__ src_idx,
                const int*   __restrict__ dst_idx,
                const float* __restrict__ W1,
                const float* __restrict__ b1,
                const float* __restrict__ W2,
                const float* __restrict__ b2,
                float*       __restrict__ out)
{
    extern __shared__ float smem[];
    float* s_inp = smem + S_INP;
    float* s_w   = smem + S_W;
    float* s_hid = smem + S_HID;

    const int tid = threadIdx.x;
    const int tx  = tid & 15;        // column group 0..15
    const int ty  = tid >> 4;        // row group 0..15 (4 rows each)
    const int ty4 = ty * 4;
    const int e0  = blockIdx.x * TILE_E;

    // ---------------- Gather phase: build inp tile [64][257] -----------------
    // Row layout: cols [0,128) = h[dst], [128,256) = h[src], col 256 = dR.
    {
        const float4* h4 = reinterpret_cast<const float4*>(h);
        #pragma unroll
        for (int idx = tid; idx < TILE_E * 64; idx += NTHREADS) {
            int row = idx >> 6;           // edge within tile
            int q   = idx & 63;           // float4 slot: 0..31 dst, 32..63 src
            int e   = e0 + row;
            float4 v;
            if (q < 32) v = h4[dst_idx[e] * 32 + q];
            else        v = h4[src_idx[e] * 32 + (q - 32)];
            // dst part -> cols q*4 (0..124); src part -> 128+(q-32)*4 = q*4. Same!
            *reinterpret_cast<float4*>(&s_inp[row * LDI + q * 4]) = v;
        }
        if (tid < TILE_E) s_inp[tid * LDI + 256] = dR[e0 + tid];
    }
    __syncthreads();

    // ---------------- GEMM1: hid[64][192] = relu(inp @ W1 + b1) --------------
    // Per thread: 4 rows (ty4..ty4+3) x 12 cols (tx + 16c), packed as 6 f32x2.
    unsigned long long acc1[4][6];
    #pragma unroll
    for (int i = 0; i < 4; ++i)
        #pragma unroll
        for (int c = 0; c < 6; ++c) acc1[i][c] = 0ull;

    for (int t = 0; t < 16; ++t) {       // k tiles of 16 over k=0..255
        const int k0 = t * 16;
        __syncthreads();                 // protect s_w from previous tile's readers
        #pragma unroll
        for (int j = tid; j < 16 * MID; j += NTHREADS)
            s_w[j] = W1[k0 * MID + j];   // contiguous, coalesced
        __syncthreads();

        #pragma unroll
        for (int kk = 0; kk < 16; ++kk) {
            const float* wrow = &s_w[kk * MID + tx];
            unsigned long long pb[6];
            #pragma unroll
            for (int c = 0; c < 6; ++c)
                pb[c] = pk2(wrow[32 * c], wrow[32 * c + 16]);

            const int k = k0 + kk;
            #pragma unroll
            for (int i = 0; i < 4; ++i) {
                float a = s_inp[(ty4 + i) * LDI + k];
                unsigned long long pa = pk2(a, a);
                #pragma unroll
                for (int c = 0; c < 6; ++c) fma2(acc1[i][c], pa, pb[c]);
            }
        }
    }

    // Epilogue GEMM1: fold k=256 (dR column), bias, relu -> s_hid
    {
        float wl[12], bi[12];
        #pragma unroll
        for (int c = 0; c < 12; ++c) {
            wl[c] = W1[256 * MID + tx + 16 * c];
            bi[c] = b1[tx + 16 * c];
        }
        #pragma unroll
        for (int i = 0; i < 4; ++i) {
            const int row = ty4 + i;
            const float ar = s_inp[row * LDI + 256];
            #pragma unroll
            for (int c = 0; c < 6; ++c) {
                float lo, hi;
                upk2(acc1[i][c], lo, hi);
                float v0 = fmaf(ar, wl[2 * c],     lo) + bi[2 * c];
                float v1 = fmaf(ar, wl[2 * c + 1], hi) + bi[2 * c + 1];
                v0 = fmaxf(v0, 0.0f);
                v1 = fmaxf(v1, 0.0f);
                s_hid[row * LDH + tx + 32 * c]      = v0;
                s_hid[row * LDH + tx + 32 * c + 16] = v1;
            }
        }
    }
    // visibility of s_hid + s_w reuse handled by sync at top of next loop

    // ---------------- GEMM2: out[64][128] = tanh(hid @ W2 + b2) --------------
    unsigned long long acc2[4][4];
    #pragma unroll
    for (int i = 0; i < 4; ++i)
        #pragma unroll
        for (int c = 0; c < 4; ++c) acc2[i][c] = 0ull;

    for (int t = 0; t < 12; ++t) {       // k tiles of 16 over k=0..191
        const int k0 = t * 16;
        __syncthreads();
        #pragma unroll
        for (int j = tid; j < 16 * OUTD; j += NTHREADS)
            s_w[j] = W2[k0 * OUTD + j];
        __syncthreads();

        #pragma unroll
        for (int kk = 0; kk < 16; ++kk) {
            const float* wrow = &s_w[kk * OUTD + tx];
            unsigned long long pb[4];
            #pragma unroll
            for (int c = 0; c < 4; ++c)
                pb[c] = pk2(wrow[32 * c], wrow[32 * c + 16]);

            const int k = k0 + kk;
            #pragma unroll
            for (int i = 0; i < 4; ++i) {
                float a = s_hid[(ty4 + i) * LDH + k];
                unsigned long long pa = pk2(a, a);
                #pragma unroll
                for (int c = 0; c < 4; ++c) fma2(acc2[i][c], pa, pb[c]);
            }
        }
    }

    // Epilogue GEMM2: bias + tanh -> global
    {
        float bi[8];
        #pragma unroll
        for (int c = 0; c < 8; ++c) bi[c] = b2[tx + 16 * c];
        #pragma unroll
        for (int i = 0; i < 4; ++i) {
            const int e = e0 + ty4 + i;
            float* orow = out + (long long)e * OUTD;
            #pragma unroll
            for (int c = 0; c < 4; ++c) {
                float lo, hi;
                upk2(acc2[i][c], lo, hi);
                orow[tx + 32 * c]      = tanhf(lo + bi[2 * c]);
                orow[tx + 32 * c + 16] = tanhf(hi + bi[2 * c + 1]);
            }
        }
    }
}

extern "C" void kernel_launch(void* const* d_in, const int* in_sizes, int n_in,
                              void* d_out, int out_size) {
    const float* h   = (const float*)d_in[0];
    const float* dR  = (const float*)d_in[1];
    const int*   src = (const int*)  d_in[2];
    const int*   dst = (const int*)  d_in[3];
    const float* W1  = (const float*)d_in[4];
    const float* b1  = (const float*)d_in[5];
    const float* W2  = (const float*)d_in[6];
    const float* b2  = (const float*)d_in[7];
    float* out = (float*)d_out;

    const int smem_bytes = SMEM_FLOATS * (int)sizeof(float);  // 129024
    cudaFuncSetAttribute(edge_mlp_kernel,
                         cudaFuncAttributeMaxDynamicSharedMemorySize, smem_bytes);

    const int nblocks = E_TOTAL / TILE_E;   // 10000
    edge_mlp_kernel<<<nblocks, NTHREADS, smem_bytes>>>(
        h, dR, src, dst, W1, b1, W2, b2, out);
}

// round 5
// speedup vs baseline: 2.2247x; 2.2247x over previous
#include <cuda_runtime.h>
#include <cuda_bf16.h>

// EdgeNetwork restructured:
//   P[node] = [h@W1_top | h@W1_mid]   (100000 x 384, fp32, precomputed)
//   out[e]  = tanh(relu(P[dst,0:192] + P[src,192:384] + dR*W1[256,:] + b1) @ W2 + b2)
// Both GEMMs: fp32 SIMT with packed fma.rn.f32x2 (round-0 proven pattern).

#define N_NODES 100000
#define E_TOTAL 640000
#define MIDN    192
#define OUTN    128

__device__ float gP[(size_t)N_NODES * 384];   // projected node features

// ---- packed f32x2 helpers ----
__device__ __forceinline__ unsigned long long pk2(float lo, float hi) {
    unsigned long long r;
    asm("mov.b64 %0, {%1, %2};" : "=l"(r) : "f"(lo), "f"(hi));
    return r;
}
__device__ __forceinline__ void upk2(unsigned long long v, float& lo, float& hi) {
    asm("mov.b64 {%0, %1}, %2;" : "=f"(lo), "=f"(hi) : "l"(v));
}
__device__ __forceinline__ void fma2(unsigned long long& d,
                                     unsigned long long a,
                                     unsigned long long b) {
    asm("fma.rn.f32x2 %0, %1, %2, %0;" : "+l"(d) : "l"(a), "l"(b));
}

// ================= proj kernel: P = [h@W1_top | h@W1_mid] =================
// Tile: 64 nodes x 384 cols (2 halves of 192), K=128. 256 threads.
// smem floats: s_a [64][132] @0 (8448), s_w [16][192] @8448 (3072) = 11520 fl.
#define PJ_SA 0
#define PJ_SW 8448
#define PJ_SMEM_BYTES (11520 * 4)

__global__ void __launch_bounds__(256, 2)
proj_kernel(const float* __restrict__ h, const float* __restrict__ W1) {
    extern __shared__ float sp[];
    float* s_a = sp + PJ_SA;
    float* s_w = sp + PJ_SW;

    const int tid = threadIdx.x;
    const int tx  = tid & 15;
    const int ty4 = (tid >> 4) * 4;
    const int m0  = blockIdx.x * 64;

    // load h tile [64][128] -> s_a (pitch 132)
    {
        const float4* h4 = reinterpret_cast<const float4*>(h);
#pragma unroll
        for (int j = 0; j < 8; ++j) {
            int idx = tid + j * 256;
            int row = idx >> 5, q = idx & 31;
            int m = m0 + row;
            float4 v = (m < N_NODES) ? h4[(size_t)m * 32 + q]
                                     : make_float4(0.f, 0.f, 0.f, 0.f);
            *reinterpret_cast<float4*>(&s_a[row * 132 + q * 4]) = v;
        }
    }
    __syncthreads();

    for (int half = 0; half < 2; ++half) {
        unsigned long long acc[4][6];
#pragma unroll
        for (int i = 0; i < 4; ++i)
#pragma unroll
            for (int c = 0; c < 6; ++c) acc[i][c] = 0ull;

        for (int t = 0; t < 8; ++t) {          // K tiles of 16 over 128
            const int k0 = t * 16;
            __syncthreads();
#pragma unroll
            for (int j = tid; j < 16 * 192; j += 256)
                s_w[j] = W1[(half * 128 + k0) * 192 + j];   // contiguous rows
            __syncthreads();

#pragma unroll
            for (int kk = 0; kk < 16; ++kk) {
                const float* wrow = &s_w[kk * 192 + tx];
                unsigned long long pb[6];
#pragma unroll
                for (int c = 0; c < 6; ++c)
                    pb[c] = pk2(wrow[32 * c], wrow[32 * c + 16]);
                const int k = k0 + kk;
#pragma unroll
                for (int i = 0; i < 4; ++i) {
                    float a = s_a[(ty4 + i) * 132 + k];
                    unsigned long long pa = pk2(a, a);
#pragma unroll
                    for (int c = 0; c < 6; ++c) fma2(acc[i][c], pa, pb[c]);
                }
            }
        }

        // epilogue: write P (no bias)
#pragma unroll
        for (int i = 0; i < 4; ++i) {
            int m = m0 + ty4 + i;
            if (m < N_NODES) {
                float* prow = gP + (size_t)m * 384 + half * 192;
#pragma unroll
                for (int c = 0; c < 6; ++c) {
                    float lo, hi;
                    upk2(acc[i][c], lo, hi);
                    prow[tx + 32 * c]      = lo;
                    prow[tx + 32 * c + 16] = hi;
                }
            }
        }
    }
}

// ================= edge kernel =================
// Tile: 64 edges. Phase A: hid = relu(P_d + P_s + dR*w1l + b1) -> s_hid.
// Phase B: out = tanh(hid @ W2 + b2)  (round-0 GEMM2 verbatim).
// smem floats: s_hid [64][196] @0 (12544), s_w [16][128] @12544 (2048),
//              s_b1 @14592 (192), s_w1l @14784 (192) -> 14976 floats.
#define EK_HID  0
#define EK_W    12544
#define EK_B1   14592
#define EK_W1L  14784
#define EK_SMEM_BYTES (14976 * 4)

__global__ void __launch_bounds__(256, 3)
edge_kernel(const float* __restrict__ dR,
            const int* __restrict__ src_idx, const int* __restrict__ dst_idx,
            const float* __restrict__ W1, const float* __restrict__ b1,
            const float* __restrict__ W2, const float* __restrict__ b2,
            float* __restrict__ out) {
    extern __shared__ float sp[];
    float* s_hid = sp + EK_HID;
    float* s_w   = sp + EK_W;
    float* s_b1  = sp + EK_B1;
    float* s_w1l = sp + EK_W1L;

    const int tid = threadIdx.x;
    const int tx  = tid & 15;
    const int ty4 = (tid >> 4) * 4;
    const int e0  = blockIdx.x * 64;

    if (tid < 192) {
        s_b1[tid]  = b1[tid];
        s_w1l[tid] = W1[256 * 192 + tid];
    }
    __syncthreads();

    // ---- phase A: gather P halves, fuse dR/bias/relu ----
    {
        const int q = tid & 3, r = tid >> 2;      // 4 threads per edge
        const int e = e0 + r;
        const int nd = dst_idx[e], ns = src_idx[e];
        const float dRr = dR[e];
        const float4* pd = reinterpret_cast<const float4*>(gP + (size_t)nd * 384) + q * 12;
        const float4* ps = reinterpret_cast<const float4*>(gP + (size_t)ns * 384 + 192) + q * 12;
#pragma unroll 4
        for (int i = 0; i < 12; ++i) {
            const int n = q * 48 + i * 4;
            float4 a = pd[i], b = ps[i];
            float4 v;
            v.x = fmaxf(a.x + b.x + dRr * s_w1l[n]     + s_b1[n],     0.f);
            v.y = fmaxf(a.y + b.y + dRr * s_w1l[n + 1] + s_b1[n + 1], 0.f);
            v.z = fmaxf(a.z + b.z + dRr * s_w1l[n + 2] + s_b1[n + 2], 0.f);
            v.w = fmaxf(a.w + b.w + dRr * s_w1l[n + 3] + s_b1[n + 3], 0.f);
            *reinterpret_cast<float4*>(&s_hid[r * 196 + n]) = v;
        }
    }

    // ---- phase B: GEMM2 (round-0 pattern) ----
    unsigned long long acc2[4][4];
#pragma unroll
    for (int i = 0; i < 4; ++i)
#pragma unroll
        for (int c = 0; c < 4; ++c) acc2[i][c] = 0ull;

    for (int t = 0; t < 12; ++t) {     // K tiles of 16 over 192
        const int k0 = t * 16;
        __syncthreads();               // t=0: also fences phase-A s_hid writes
#pragma unroll
        for (int j = tid; j < 16 * 128; j += 256)
            s_w[j] = W2[k0 * 128 + j];
        __syncthreads();

#pragma unroll
        for (int kk = 0; kk < 16; ++kk) {
            const float* wrow = &s_w[kk * 128 + tx];
            unsigned long long pb[4];
#pragma unroll
            for (int c = 0; c < 4; ++c)
                pb[c] = pk2(wrow[32 * c], wrow[32 * c + 16]);
            const int k = k0 + kk;
#pragma unroll
            for (int i = 0; i < 4; ++i) {
                float a = s_hid[(ty4 + i) * 196 + k];
                unsigned long long pa = pk2(a, a);
#pragma unroll
                for (int c = 0; c < 4; ++c) fma2(acc2[i][c], pa, pb[c]);
            }
        }
    }

    // epilogue: bias + tanh -> global
    {
        float bi[8];
#pragma unroll
        for (int c = 0; c < 8; ++c) bi[c] = b2[tx + 16 * c];
#pragma unroll
        for (int i = 0; i < 4; ++i) {
            const int e = e0 + ty4 + i;
            float* orow = out + (size_t)e * OUTN;
#pragma unroll
            for (int c = 0; c < 4; ++c) {
                float lo, hi;
                upk2(acc2[i][c], lo, hi);
                orow[tx + 32 * c]      = tanhf(lo + bi[2 * c]);
                orow[tx + 32 * c + 16] = tanhf(hi + bi[2 * c + 1]);
            }
        }
    }
}

extern "C" void kernel_launch(void* const* d_in, const int* in_sizes, int n_in,
                              void* d_out, int out_size) {
    const float* h   = (const float*)d_in[0];
    const float* dR  = (const float*)d_in[1];
    const int*   src = (const int*)  d_in[2];
    const int*   dst = (const int*)  d_in[3];
    const float* W1  = (const float*)d_in[4];
    const float* b1  = (const float*)d_in[5];
    const float* W2  = (const float*)d_in[6];
    const float* b2  = (const float*)d_in[7];
    float* out = (float*)d_out;

    cudaFuncSetAttribute(proj_kernel,
                         cudaFuncAttributeMaxDynamicSharedMemorySize, PJ_SMEM_BYTES);
    cudaFuncSetAttribute(edge_kernel,
                         cudaFuncAttributeMaxDynamicSharedMemorySize, EK_SMEM_BYTES);

    proj_kernel<<<(N_NODES + 63) / 64, 256, PJ_SMEM_BYTES>>>(h, W1);
    edge_kernel<<<E_TOTAL / 64, 256, EK_SMEM_BYTES>>>(dR, src, dst, W1, b1, W2, b2, out);
}

// round 6
// speedup vs baseline: 2.2921x; 1.0303x over previous
#include <cuda_runtime.h>
#include <cuda_bf16.h>

// EdgeNetwork restructured:
//   P[node] = [h@W1_top | h@W1_mid]   (100000 x 384, fp32, precomputed)
//   out[e]  = tanh(relu(P[dst,0:192] + P[src,192:384] + dR*W1[256,:] + b1) @ W2 + b2)
// fp32 SIMT, packed fma.rn.f32x2; B operands via LDS.64 pairs, A via LDS.128.

#define N_NODES 100000
#define E_TOTAL 640000
#define MIDN    192
#define OUTN    128

__device__ float gP[(size_t)N_NODES * 384];   // projected node features

typedef unsigned long long ull;

__device__ __forceinline__ ull pk2(float lo, float hi) {
    ull r;
    asm("mov.b64 %0, {%1, %2};" : "=l"(r) : "f"(lo), "f"(hi));
    return r;
}
__device__ __forceinline__ void upk2(ull v, float& lo, float& hi) {
    asm("mov.b64 {%0, %1}, %2;" : "=f"(lo), "=f"(hi) : "l"(v));
}
__device__ __forceinline__ void fma2(ull& d, ull a, ull b) {
    asm("fma.rn.f32x2 %0, %1, %2, %0;" : "+l"(d) : "l"(a), "l"(b));
}

// ================= proj kernel: P = [h@W1_top | h@W1_mid] =================
// Tile: 64 nodes x 384 cols (2 halves of 192), K=128. 256 threads.
// smem floats: s_a [64][132] @0 (8448), s_w [16][192] @8448 (3072) = 11520.
#define PJ_SA 0
#define PJ_SW 8448
#define PJ_SMEM_BYTES (11520 * 4)

__global__ void __launch_bounds__(256, 2)
proj_kernel(const float* __restrict__ h, const float* __restrict__ W1) {
    extern __shared__ float sp[];
    float* s_a = sp + PJ_SA;
    float* s_w = sp + PJ_SW;

    const int tid = threadIdx.x;
    const int tx2 = (tid & 15) * 2;          // column pair base
    const int ty4 = (tid >> 4) * 4;
    const int m0  = blockIdx.x * 64;

    // load h tile [64][128] -> s_a (pitch 132)
    {
        const float4* h4 = reinterpret_cast<const float4*>(h);
#pragma unroll
        for (int j = 0; j < 8; ++j) {
            int idx = tid + j * 256;
            int row = idx >> 5, q = idx & 31;
            int m = m0 + row;
            float4 v = (m < N_NODES) ? h4[(size_t)m * 32 + q]
                                     : make_float4(0.f, 0.f, 0.f, 0.f);
            *reinterpret_cast<float4*>(&s_a[row * 132 + q * 4]) = v;
        }
    }
    __syncthreads();

    for (int half = 0; half < 2; ++half) {
        ull acc[4][6];
#pragma unroll
        for (int i = 0; i < 4; ++i)
#pragma unroll
            for (int c = 0; c < 6; ++c) acc[i][c] = 0ull;

        for (int t = 0; t < 8; ++t) {          // K tiles of 16 over 128
            const int k0 = t * 16;
            __syncthreads();
#pragma unroll
            for (int j = 0; j < 3; ++j) {
                int idx = tid + j * 256;       // 768 float4 = 3072 floats
                reinterpret_cast<float4*>(s_w)[idx] =
                    reinterpret_cast<const float4*>(W1 + (half * 128 + k0) * 192)[idx];
            }
            __syncthreads();

#pragma unroll
            for (int kq = 0; kq < 4; ++kq) {
                float4 av[4];
#pragma unroll
                for (int i = 0; i < 4; ++i)
                    av[i] = *reinterpret_cast<const float4*>(
                        &s_a[(ty4 + i) * 132 + k0 + kq * 4]);
#pragma unroll
                for (int kk = 0; kk < 4; ++kk) {
                    const float* wrow = &s_w[(kq * 4 + kk) * 192 + tx2];
                    ull pb[6];
#pragma unroll
                    for (int c = 0; c < 6; ++c)
                        pb[c] = *reinterpret_cast<const ull*>(wrow + 32 * c);
#pragma unroll
                    for (int i = 0; i < 4; ++i) {
                        float a = reinterpret_cast<const float*>(&av[i])[kk];
                        ull pa = pk2(a, a);
#pragma unroll
                        for (int c = 0; c < 6; ++c) fma2(acc[i][c], pa, pb[c]);
                    }
                }
            }
        }

        // epilogue: write P (no bias), contiguous float2 per pair
#pragma unroll
        for (int i = 0; i < 4; ++i) {
            int m = m0 + ty4 + i;
            if (m < N_NODES) {
                float* prow = gP + (size_t)m * 384 + half * 192;
#pragma unroll
                for (int c = 0; c < 6; ++c) {
                    float lo, hi;
                    upk2(acc[i][c], lo, hi);
                    *reinterpret_cast<float2*>(prow + tx2 + 32 * c) =
                        make_float2(lo, hi);
                }
            }
        }
    }
}

// ================= edge kernel =================
// Tile: 64 edges. Phase A: hid = relu(P_d + P_s + dR*w1l + b1) -> s_hid.
// Phase B: out = tanh(hid @ W2 + b2).
// smem floats: s_hid [64][196] @0, s_w [16][128] @12544, s_b1 @14592,
//              s_w1l @14784 -> 14976 floats = 59904 B.
#define EK_HID  0
#define EK_W    12544
#define EK_B1   14592
#define EK_W1L  14784
#define EK_SMEM_BYTES (14976 * 4)

__global__ void __launch_bounds__(256, 3)
edge_kernel(const float* __restrict__ dR,
            const int* __restrict__ src_idx, const int* __restrict__ dst_idx,
            const float* __restrict__ W1, const float* __restrict__ b1,
            const float* __restrict__ W2, const float* __restrict__ b2,
            float* __restrict__ out) {
    extern __shared__ float sp[];
    float* s_hid = sp + EK_HID;
    float* s_w   = sp + EK_W;
    float* s_b1  = sp + EK_B1;
    float* s_w1l = sp + EK_W1L;

    const int tid = threadIdx.x;
    const int tx2 = (tid & 15) * 2;
    const int ty4 = (tid >> 4) * 4;
    const int e0  = blockIdx.x * 64;

    if (tid < 192) {
        s_b1[tid]  = b1[tid];
        s_w1l[tid] = W1[256 * 192 + tid];
    }
    __syncthreads();

    // ---- phase A: gather P halves, fuse dR/bias/relu ----
    {
        const int q = tid & 3, r = tid >> 2;      // 4 threads per edge
        const int e = e0 + r;
        const int nd = dst_idx[e], ns = src_idx[e];
        const float dRr = dR[e];
        const float4* pd = reinterpret_cast<const float4*>(gP + (size_t)nd * 384) + q * 12;
        const float4* ps = reinterpret_cast<const float4*>(gP + (size_t)ns * 384 + 192) + q * 12;
#pragma unroll 4
        for (int i = 0; i < 12; ++i) {
            const int n = q * 48 + i * 4;
            float4 a = pd[i], b = ps[i];
            float4 v;
            v.x = fmaxf(a.x + b.x + dRr * s_w1l[n]     + s_b1[n],     0.f);
            v.y = fmaxf(a.y + b.y + dRr * s_w1l[n + 1] + s_b1[n + 1], 0.f);
            v.z = fmaxf(a.z + b.z + dRr * s_w1l[n + 2] + s_b1[n + 2], 0.f);
            v.w = fmaxf(a.w + b.w + dRr * s_w1l[n + 3] + s_b1[n + 3], 0.f);
            *reinterpret_cast<float4*>(&s_hid[r * 196 + n]) = v;
        }
    }

    // ---- phase B: GEMM2 ----
    ull acc2[4][4];
#pragma unroll
    for (int i = 0; i < 4; ++i)
#pragma unroll
        for (int c = 0; c < 4; ++c) acc2[i][c] = 0ull;

    for (int t = 0; t < 12; ++t) {     // K tiles of 16 over 192
        const int k0 = t * 16;
        __syncthreads();               // t=0: also fences phase-A s_hid writes
        {
            int idx = tid;             // 512 float4 = 2048 floats
            reinterpret_cast<float4*>(s_w)[idx] =
                reinterpret_cast<const float4*>(W2 + k0 * 128)[idx];
            idx += 256;
            reinterpret_cast<float4*>(s_w)[idx] =
                reinterpret_cast<const float4*>(W2 + k0 * 128)[idx];
        }
        __syncthreads();

#pragma unroll
        for (int kq = 0; kq < 4; ++kq) {
            float4 av[4];
#pragma unroll
            for (int i = 0; i < 4; ++i)
                av[i] = *reinterpret_cast<const float4*>(
                    &s_hid[(ty4 + i) * 196 + k0 + kq * 4]);
#pragma unroll
            for (int kk = 0; kk < 4; ++kk) {
                const float* wrow = &s_w[(kq * 4 + kk) * 128 + tx2];
                ull pb[4];
#pragma unroll
                for (int c = 0; c < 4; ++c)
                    pb[c] = *reinterpret_cast<const ull*>(wrow + 32 * c);
#pragma unroll
                for (int i = 0; i < 4; ++i) {
                    float a = reinterpret_cast<const float*>(&av[i])[kk];
                    ull pa = pk2(a, a);
#pragma unroll
                    for (int c = 0; c < 4; ++c) fma2(acc2[i][c], pa, pb[c]);
                }
            }
        }
    }

    // epilogue: bias + tanh -> global, float2 stores
    {
        float2 bi[4];
#pragma unroll
        for (int c = 0; c < 4; ++c)
            bi[c] = *reinterpret_cast<const float2*>(b2 + tx2 + 32 * c);
#pragma unroll
        for (int i = 0; i < 4; ++i) {
            const int e = e0 + ty4 + i;
            float* orow = out + (size_t)e * OUTN;
#pragma unroll
            for (int c = 0; c < 4; ++c) {
                float lo, hi;
                upk2(acc2[i][c], lo, hi);
                *reinterpret_cast<float2*>(orow + tx2 + 32 * c) =
                    make_float2(tanhf(lo + bi[c].x), tanhf(hi + bi[c].y));
            }
        }
    }
}

extern "C" void kernel_launch(void* const* d_in, const int* in_sizes, int n_in,
                              void* d_out, int out_size) {
    const float* h   = (const float*)d_in[0];
    const float* dR  = (const float*)d_in[1];
    const int*   src = (const int*)  d_in[2];
    const int*   dst = (const int*)  d_in[3];
    const float* W1  = (const float*)d_in[4];
    const float* b1  = (const float*)d_in[5];
    const float* W2  = (const float*)d_in[6];
    const float* b2  = (const float*)d_in[7];
    float* out = (float*)d_out;

    cudaFuncSetAttribute(proj_kernel,
                         cudaFuncAttributeMaxDynamicSharedMemorySize, PJ_SMEM_BYTES);
    cudaFuncSetAttribute(edge_kernel,
                         cudaFuncAttributeMaxDynamicSharedMemorySize, EK_SMEM_BYTES);

    proj_kernel<<<(N_NODES + 63) / 64, 256, PJ_SMEM_BYTES>>>(h, W1);
    edge_kernel<<<E_TOTAL / 64, 256, EK_SMEM_BYTES>>>(dR, src, dst, W1, b1, W2, b2, out);
}